// round 7
// baseline (speedup 1.0000x reference)
#include <cuda_runtime.h>
#include <cstdint>

#define LRELU_ALPHA 0.2f

typedef unsigned long long u64;

// packed f32x2 helpers (sm_103a FFMA2 is PTX-only)
__device__ __forceinline__ void ffma2(u64 &d, u64 a, u64 b){
    asm("fma.rn.f32x2 %0, %1, %2, %0;" : "+l"(d) : "l"(a), "l"(b));
}
__device__ __forceinline__ u64 pack2(float s){
    u64 d; asm("mov.b64 %0, {%1, %1};" : "=l"(d) : "f"(s)); return d;
}
__device__ __forceinline__ void unpack2(float &lo, float &hi, u64 v){
    asm("mov.b64 {%0,%1}, %2;" : "=f"(lo), "=f"(hi) : "l"(v));
}
__device__ __forceinline__ float hsum2(u64 v){
    float lo, hi;
    asm("mov.b64 {%0,%1}, %2;" : "=f"(lo), "=f"(hi) : "l"(v));
    return lo + hi;
}

// ping-pong activation buffers (allocation-free scratch)
__device__ __align__(16) float g_bufA[67108864];   // h1, h3, d1, d3
__device__ __align__(16) float g_bufB[33554432];   // h2, q,  d2

// ---------------------------------------------------------------------------
// ci-paired stride-2 transposed conv (lhs_dilation=2, pad=(2,1)), NHWC.
// f32x2 lanes = (even ci, odd ci) partial sums -> x loads are DIRECT LDG.128
// (no duplication MOVs); weights staged in smem pair-interleaved
// [tap][cipair][co][2] so the thread's wpair is one LDS.128 (conflict-free:
// lanes' 16B units contiguous).
// Thread = 2 couts x RP cols x 2 rows (h0 even, h0+1 odd).
// Column taps: col 2u: kx0*xcol[u] + kx2*xcol[u+1]; col 2u+1: kx1*xcol[u+1],
// where xcol[c] = x[iwb-1+c]. Row taps: row h0 <- ky0(rowA)+ky2(rowB);
// row h0+1 <- ky1(rowB). Weights per tile of CC=32 ci (synced double loop).
// ---------------------------------------------------------------------------
template<int CI, int CO, int RPH>
__device__ __forceinline__ void apply_row_dc(
    u64 (&acc)[2*RPH][2], const float* __restrict__ sw, int tapbase,
    const float* __restrict__ row, int iwb, bool left, int cq, int cp4)
{
    const int cpA = cp4 >> 1;
    const float* wb = sw + 2*(2*cq);
    ulonglong2 w0a = *reinterpret_cast<const ulonglong2*>(wb + (((tapbase+0)*16 + cpA  )*CO)*2);
    ulonglong2 w0b = *reinterpret_cast<const ulonglong2*>(wb + (((tapbase+0)*16 + cpA+1)*CO)*2);
    ulonglong2 w1a = *reinterpret_cast<const ulonglong2*>(wb + (((tapbase+1)*16 + cpA  )*CO)*2);
    ulonglong2 w1b = *reinterpret_cast<const ulonglong2*>(wb + (((tapbase+1)*16 + cpA+1)*CO)*2);
    ulonglong2 w2a = *reinterpret_cast<const ulonglong2*>(wb + (((tapbase+2)*16 + cpA  )*CO)*2);
    ulonglong2 w2b = *reinterpret_cast<const ulonglong2*>(wb + (((tapbase+2)*16 + cpA+1)*CO)*2);

    #pragma unroll
    for (int c = 0; c <= RPH; c++){
        ulonglong2 xv;
        if (c == 0 && !left){ xv.x = 0ull; xv.y = 0ull; }
        else xv = *reinterpret_cast<const ulonglong2*>(row + (size_t)(iwb-1+c)*CI + cp4);
        if (c < RPH){          // kx0 -> even col 2c
            ffma2(acc[2*c][0], w0a.x, xv.x); ffma2(acc[2*c][1], w0a.y, xv.x);
            ffma2(acc[2*c][0], w0b.x, xv.y); ffma2(acc[2*c][1], w0b.y, xv.y);
        }
        if (c >= 1){           // kx2 -> even col 2(c-1); kx1 -> odd col 2(c-1)+1
            ffma2(acc[2*c-2][0], w2a.x, xv.x); ffma2(acc[2*c-2][1], w2a.y, xv.x);
            ffma2(acc[2*c-2][0], w2b.x, xv.y); ffma2(acc[2*c-2][1], w2b.y, xv.y);
            ffma2(acc[2*c-1][0], w1a.x, xv.x); ffma2(acc[2*c-1][1], w1a.y, xv.x);
            ffma2(acc[2*c-1][0], w1b.x, xv.y); ffma2(acc[2*c-1][1], w1b.y, xv.y);
        }
    }
}

template<int CI, int CO, int RP>
__global__ __launch_bounds__(256) void deconvT_kernel(
    const float* __restrict__ in, const float* __restrict__ w,
    const float* __restrict__ bias, float* __restrict__ out,
    int N, int Hin, int Win, int Hout, int Wout)
{
    extern __shared__ float sw[];          // [9][16][CO][2] floats per ci-tile
    constexpr int CC  = 32;                // ci tile
    constexpr int NT  = CI / CC;
    constexpr int CQ  = CO / 2;
    constexpr int GB  = 256 / CQ;
    constexpr int RPH = RP / 2;
    static_assert(CI % CC == 0 && CO % 2 == 0 && RP % 2 == 0, "");

    const int cq = threadIdx.x % CQ;
    const int g  = threadIdx.x / CQ;
    const int w0 = (blockIdx.x * GB + g) * RP;
    const int h0 = blockIdx.y * 2;
    const int n  = blockIdx.z;

    const int  iwb  = w0 >> 1;
    const bool left = (iwb >= 1);
    const int  ihyA = (h0 >> 1) - 1;
    const int  ihyB = (h0 >> 1);

    u64 accE[RP][2], accO[RP][2];
    #pragma unroll
    for (int r=0;r<RP;r++){
        accE[r][0]=0ull; accE[r][1]=0ull;
        accO[r][0]=0ull; accO[r][1]=0ull;
    }

    for (int t = 0; t < NT; t++){
        const int cc = t * CC;
        if (t) __syncthreads();
        // stage weight tile: GMEM [tap][ci][co] -> smem [tap][cipair][co][2]
        for (int idx = threadIdx.x; idx < 9*CC*CO; idx += 256){
            int co  = idx % CO;
            int rst = idx / CO;
            int cil = rst % CC;
            int tap = rst / CC;
            sw[(((tap*16) + (cil>>1))*CO + co)*2 + (cil & 1)] =
                w[((size_t)tap*CI + cc + cil)*CO + co];
        }
        __syncthreads();

        const float* rowA = in + ((size_t)(n*Hin + ihyA)*Win)*CI + cc;
        const float* rowB = in + ((size_t)(n*Hin + ihyB)*Win)*CI + cc;

        #pragma unroll 2
        for (int cp4 = 0; cp4 < CC; cp4 += 4){
            if (ihyA >= 0)
                apply_row_dc<CI,CO,RPH>(accE, sw, 0, rowA, iwb, left, cq, cp4);
            apply_row_dc<CI,CO,RPH>(accE, sw, 6, rowB, iwb, left, cq, cp4);
            apply_row_dc<CI,CO,RPH>(accO, sw, 3, rowB, iwb, left, cq, cp4);
        }
    }

    const float2 bv = *reinterpret_cast<const float2*>(bias + 2*cq);
    #pragma unroll
    for (int row = 0; row < 2; row++){
        const size_t ob = ((size_t)(n*Hout + h0 + row)*Wout + w0)*CO + 2*cq;
        #pragma unroll
        for (int r = 0; r < RP; r++){
            u64 a0u = row ? accO[r][0] : accE[r][0];
            u64 a1u = row ? accO[r][1] : accE[r][1];
            float a0 = hsum2(a0u) + bv.x;
            float a1 = hsum2(a1u) + bv.y;
            a0 = (a0 > 0.f) ? a0 : LRELU_ALPHA * a0;
            a1 = (a1 > 0.f) ? a1 : LRELU_ALPHA * a1;
            float2 o; o.x = a0; o.y = a1;
            *reinterpret_cast<float2*>(out + ob + (size_t)r*CO) = o;
        }
    }
}

// ---------------------------------------------------------------------------
// R3/R6 conv kernel (encoder): stride-2 SAME conv (pad_lo=0), 4 couts x RP cols
// ---------------------------------------------------------------------------
template<int S, int DIL, int PAD, int CI, int CO, int RP, bool RELU>
__global__ __launch_bounds__(256) void conv4_kernel(
    const float* __restrict__ in, const float* __restrict__ w,
    const float* __restrict__ bias, float* __restrict__ out,
    int N, int Hin, int Win, int Hout, int Wout)
{
    constexpr int CQ = CO / 4;
    constexpr int G  = 256 / CQ;
    static_assert(RP % 2 == 0, "RP even");

    const int cq = threadIdx.x % CQ;
    const int g  = threadIdx.x / CQ;
    const int w0 = (blockIdx.x * G + g) * RP;
    const int h  = blockIdx.y;
    const int n  = blockIdx.z;
    if (w0 >= Wout) return;

    u64 acc0[RP], acc1[RP];
    #pragma unroll
    for (int r=0;r<RP;r++){ acc0[r]=0ull; acc1[r]=0ull; }

    #pragma unroll
    for (int ky=0; ky<3; ky++){
        int ihy = h*S + ky;
        if (ihy >= Hin) continue;
        const float* __restrict__ rowp = in + (size_t)(n*Hin + ihy) * Win * CI;

        #pragma unroll
        for (int kx=0; kx<3; kx++){
            const float* __restrict__ wp = w + (size_t)((ky*3+kx)*CI) * CO + 4*cq;
            int  ofs[RP];
            bool v[RP];
            #pragma unroll
            for (int r=0;r<RP;r++){
                int iw = (w0+r)*S + kx;
                v[r]   = (iw < Win);
                ofs[r] = v[r] ? iw*CI : 0;
            }

            if constexpr (CI % 4 == 0) {
                #pragma unroll 2
                for (int ci=0; ci<CI; ci+=4){
                    ulonglong2 wv0 = *reinterpret_cast<const ulonglong2*>(wp + (size_t)(ci+0)*CO);
                    ulonglong2 wv1 = *reinterpret_cast<const ulonglong2*>(wp + (size_t)(ci+1)*CO);
                    ulonglong2 wv2 = *reinterpret_cast<const ulonglong2*>(wp + (size_t)(ci+2)*CO);
                    ulonglong2 wv3 = *reinterpret_cast<const ulonglong2*>(wp + (size_t)(ci+3)*CO);
                    #pragma unroll
                    for (int r=0;r<RP;r++){
                        if (v[r]){
                            float4 xv = *reinterpret_cast<const float4*>(rowp + ofs[r] + ci);
                            u64 p0 = pack2(xv.x), p1 = pack2(xv.y);
                            u64 p2 = pack2(xv.z), p3 = pack2(xv.w);
                            ffma2(acc0[r], wv0.x, p0); ffma2(acc1[r], wv0.y, p0);
                            ffma2(acc0[r], wv1.x, p1); ffma2(acc1[r], wv1.y, p1);
                            ffma2(acc0[r], wv2.x, p2); ffma2(acc1[r], wv2.y, p2);
                            ffma2(acc0[r], wv3.x, p3); ffma2(acc1[r], wv3.y, p3);
                        }
                    }
                }
            } else {
                #pragma unroll
                for (int ci=0; ci<CI; ci++){
                    ulonglong2 wv = *reinterpret_cast<const ulonglong2*>(wp + (size_t)ci*CO);
                    #pragma unroll
                    for (int r=0;r<RP;r++){
                        if (v[r]){
                            u64 p = pack2(rowp[ofs[r] + ci]);
                            ffma2(acc0[r], wv.x, p);
                            ffma2(acc1[r], wv.y, p);
                        }
                    }
                }
            }
        }
    }

    const float4 bv = *reinterpret_cast<const float4*>(bias + 4*cq);
    const size_t ob = ((size_t)(n*Hout + h)*Wout + w0)*CO + 4*cq;
    #pragma unroll
    for (int r=0;r<RP;r++){
        float a0,a1,a2,a3;
        unpack2(a0,a1,acc0[r]); unpack2(a2,a3,acc1[r]);
        a0 += bv.x; a1 += bv.y; a2 += bv.z; a3 += bv.w;
        if (RELU){
            a0 = (a0 > 0.f) ? a0 : LRELU_ALPHA * a0;
            a1 = (a1 > 0.f) ? a1 : LRELU_ALPHA * a1;
            a2 = (a2 > 0.f) ? a2 : LRELU_ALPHA * a2;
            a3 = (a3 > 0.f) ? a3 : LRELU_ALPHA * a3;
        }
        float4 o; o.x=a0; o.y=a1; o.z=a2; o.w=a3;
        *reinterpret_cast<float4*>(out + ob + (size_t)r*CO) = o;
    }
}

// ---------------------------------------------------------------------------
// fused enc4 (1x1 conv, 64->32) + vector quantization
// ---------------------------------------------------------------------------
__global__ __launch_bounds__(64) void enc4_vq_kernel(
    const float* __restrict__ h3, const float* __restrict__ w,
    const float* __restrict__ b, const float* __restrict__ cb,
    float* __restrict__ q, int NP)
{
    __shared__ float sw[2048];   // w  [64][32]
    __shared__ float scb[2048];  // cb [32][64]
    for (int i = threadIdx.x; i < 2048; i += 64){ sw[i] = w[i]; scb[i] = cb[i]; }
    __syncthreads();

    int p = blockIdx.x*blockDim.x + threadIdx.x;
    if (p >= NP) return;
    float z[32];
    #pragma unroll
    for (int d=0;d<32;d++) z[d] = b[d];
    const float* hp = h3 + (size_t)p*64;
    #pragma unroll
    for (int c4=0;c4<64;c4+=4){
        float4 hv = *reinterpret_cast<const float4*>(hp + c4);
        #pragma unroll
        for (int d=0;d<32;d++){
            z[d] += hv.x * sw[(c4+0)*32 + d];
            z[d] += hv.y * sw[(c4+1)*32 + d];
            z[d] += hv.z * sw[(c4+2)*32 + d];
            z[d] += hv.w * sw[(c4+3)*32 + d];
        }
    }
    float best = 3.4e38f; int bk = 0;
    for (int k=0;k<64;k++){
        float dist = 0.f;
        #pragma unroll
        for (int d=0;d<32;d++){
            float e = scb[d*64 + k];
            dist += e*(e - 2.f*z[d]);
        }
        if (dist < best){ best = dist; bk = k; }   // strict < == first-min (jnp.argmin)
    }
    float* qp = q + (size_t)p*32;
    #pragma unroll
    for (int d=0;d<32;d++) qp[d] = scb[d*64 + bk];
}

// ---------------------------------------------------------------------------
// dec4: conv_transpose stride 1 (== SAME conv pad 1), CI=32, CO=1.
// ---------------------------------------------------------------------------
__global__ __launch_bounds__(256) void dec4_kernel(
    const float* __restrict__ in, const float* __restrict__ w,
    const float* __restrict__ b, float* __restrict__ out,
    int N, int H, int W)
{
    int gw = (blockIdx.x * blockDim.x + threadIdx.x) >> 5;
    int lane = threadIdx.x & 31;
    int gpr = W >> 2;
    int total = N*H*gpr;
    if (gw >= total) return;
    int gx = gw % gpr; int t = gw / gpr;
    int h = t % H; int n = t / H;
    int w0 = gx*4;

    float wk[9];
    #pragma unroll
    for (int i=0;i<9;i++) wk[i] = w[i*32 + lane];

    float acc[4] = {0.f,0.f,0.f,0.f};
    #pragma unroll
    for (int ky=0;ky<3;ky++){
        int ih = h + ky - 1;
        if (ih < 0 || ih >= H) continue;
        const float* rowp = in + ((size_t)(n*H + ih)*W)*32 + lane;
        float v[6];
        #pragma unroll
        for (int c=0;c<6;c++){
            int iw = w0 - 1 + c;
            v[c] = (iw >= 0 && iw < W) ? rowp[(size_t)iw*32] : 0.f;
        }
        #pragma unroll
        for (int kx=0;kx<3;kx++)
            #pragma unroll
            for (int r=0;r<4;r++)
                acc[r] += v[r+kx] * wk[ky*3+kx];
    }
    float bv = b[0];
    #pragma unroll
    for (int r=0;r<4;r++){
        float a = acc[r];
        #pragma unroll
        for (int o=16;o;o>>=1) a += __shfl_xor_sync(0xffffffffu, a, o);
        if (lane == 0) out[((size_t)(n*H + h)*W) + w0 + r] = a + bv;
    }
}

extern "C" void kernel_launch(void* const* d_in, const int* in_sizes, int n_in,
                              void* d_out, int out_size)
{
    (void)in_sizes; (void)n_in; (void)out_size;
    const float* x   = (const float*)d_in[0];
    const float* e1w = (const float*)d_in[1];  const float* e1b = (const float*)d_in[2];
    const float* e2w = (const float*)d_in[3];  const float* e2b = (const float*)d_in[4];
    const float* e3w = (const float*)d_in[5];  const float* e3b = (const float*)d_in[6];
    const float* e4w = (const float*)d_in[7];  const float* e4b = (const float*)d_in[8];
    const float* cb  = (const float*)d_in[9];
    const float* d1w = (const float*)d_in[10]; const float* d1b = (const float*)d_in[11];
    const float* d2w = (const float*)d_in[12]; const float* d2b = (const float*)d_in[13];
    const float* d3w = (const float*)d_in[14]; const float* d3b = (const float*)d_in[15];
    const float* d4w = (const float*)d_in[16]; const float* d4b = (const float*)d_in[17];
    float* out = (float*)d_out;

    float *A, *B;
    cudaGetSymbolAddress((void**)&A, g_bufA);
    cudaGetSymbolAddress((void**)&B, g_bufB);

    // encoder: 256 -> 128 -> 64 -> 32   (R6 configs)
    conv4_kernel<2,1,0, 3,32,4,true ><<< dim3(1,128,32), 256 >>>(x, e1w, e1b, A, 32,256,256,128,128);
    conv4_kernel<2,1,0,32,64,4,true ><<< dim3(1, 64,32), 256 >>>(A, e2w, e2b, B, 32,128,128, 64, 64);
    conv4_kernel<2,1,0,64,64,2,true ><<< dim3(1, 32,32), 256 >>>(B, e3w, e3b, A, 32, 64, 64, 32, 32);

    // enc4 (1x1) + VQ fused
    enc4_vq_kernel<<< 512, 64 >>>(A, e4w, e4b, cb, B, 32768);

    // decoder (ci-paired smem-weight deconvs)
    // smem bytes = 9*16*CO*2*4
    auto dc1 = deconvT_kernel<32,64,8>;   // CQ=32, GB=8, 8*8=64 cols
    auto dc2 = deconvT_kernel<64,64,8>;   // CQ=32, GB=8, 64 cols x2 blocks
    auto dc3 = deconvT_kernel<64,32,8>;   // CQ=16, GB=16, 128 cols x2 blocks
    const int SM64 = 9*16*64*2*4;         // 73728
    const int SM32 = 9*16*32*2*4;         // 36864
    cudaFuncSetAttribute(dc1, cudaFuncAttributeMaxDynamicSharedMemorySize, SM64);
    cudaFuncSetAttribute(dc2, cudaFuncAttributeMaxDynamicSharedMemorySize, SM64);
    cudaFuncSetAttribute(dc3, cudaFuncAttributeMaxDynamicSharedMemorySize, SM32);

    dc1<<< dim3(1, 32,32), 256, SM64 >>>(B, d1w, d1b, A, 32, 32, 32, 64, 64);
    dc2<<< dim3(2, 64,32), 256, SM64 >>>(A, d2w, d2b, B, 32, 64, 64,128,128);
    dc3<<< dim3(2,128,32), 256, SM32 >>>(B, d3w, d3b, A, 32,128,128,256,256);

    // dec4: stride-1 deconv == SAME conv, CO=1
    dec4_kernel<<< 65536, 256 >>>(A, d4w, d4b, out, 32, 256, 256);
}

// round 8
// speedup vs baseline: 1.3533x; 1.3533x over previous
#include <cuda_runtime.h>
#include <cstdint>

#define LRELU_ALPHA 0.2f

typedef unsigned long long u64;

// packed f32x2 helpers (sm_103a FFMA2 is PTX-only)
__device__ __forceinline__ void ffma2(u64 &d, u64 a, u64 b){
    asm("fma.rn.f32x2 %0, %1, %2, %0;" : "+l"(d) : "l"(a), "l"(b));
}
__device__ __forceinline__ u64 pack2(float s){
    u64 d; asm("mov.b64 %0, {%1, %1};" : "=l"(d) : "f"(s)); return d;
}
__device__ __forceinline__ void unpack2(float &lo, float &hi, u64 v){
    asm("mov.b64 {%0,%1}, %2;" : "=f"(lo), "=f"(hi) : "l"(v));
}

// ping-pong activation buffers (allocation-free scratch)
__device__ __align__(16) float g_bufA[67108864];   // h1, h3, d1, d3
__device__ __align__(16) float g_bufB[33554432];   // h2, q,  d2

// ---------------------------------------------------------------------------
// Wide row-paired stride-2 transposed conv (lhs_dilation=2, pad=(2,1)), NHWC,
// w HWIO [9][CI][CO], weights from GLOBAL (L1-broadcast across the warp).
// Thread = 4 couts x RP output cols x 2 output rows (h0 even, h0+1 odd).
// x columns iwb-1 .. iwb+RP/2-1 packed ONCE per ci-chunk per input row and
// reused by both ky-applications of that row.
// Col taps: even col 2t: kx0*x[iwb-1+t] + kx2*x[iwb+t]; odd col 2t+1: kx1*x[iwb+t].
// Row taps: even row <- ky0(rowA) + ky2(rowB); odd row <- ky1(rowB).
// ---------------------------------------------------------------------------
template<int CI, int CO, int RP>
__global__ __launch_bounds__(128,3) void deconvW_kernel(
    const float* __restrict__ in, const float* __restrict__ w,
    const float* __restrict__ bias, float* __restrict__ out,
    int N, int Hin, int Win, int Hout, int Wout)
{
    constexpr int NC  = 4;
    constexpr int CQ  = CO / NC;
    constexpr int G   = 128 / CQ;
    constexpr int RPH = RP / 2;

    const int cq = threadIdx.x % CQ;
    const int g  = threadIdx.x / CQ;
    const int w0 = (blockIdx.x * G + g) * RP;
    const int h0 = blockIdx.y * 2;
    const int n  = blockIdx.z;

    const int  iwb  = w0 >> 1;
    const bool left = (iwb >= 1);
    const int  ihyA = (h0 >> 1) - 1;
    const int  ihyB = (h0 >> 1);

    u64 accE[RP][2], accO[RP][2];
    #pragma unroll
    for (int r=0;r<RP;r++){
        accE[r][0]=0ull; accE[r][1]=0ull;
        accO[r][0]=0ull; accO[r][1]=0ull;
    }

    const float* __restrict__ wp = w + 4*cq;

    // apply one ky row of weights (all 3 kx taps) for 4 ci, given packed x cols
    auto apply_ky = [&](u64 (&acc)[RP][2], int ky, int ci, const u64 (*px)[4]){
        #pragma unroll
        for (int c=0;c<4;c++){
            ulonglong2 wv0 = *reinterpret_cast<const ulonglong2*>(wp + (size_t)((ky*3+0)*CI + ci + c)*CO);
            ulonglong2 wv1 = *reinterpret_cast<const ulonglong2*>(wp + (size_t)((ky*3+1)*CI + ci + c)*CO);
            ulonglong2 wv2 = *reinterpret_cast<const ulonglong2*>(wp + (size_t)((ky*3+2)*CI + ci + c)*CO);
            #pragma unroll
            for (int t=0;t<RPH;t++){       // kx0 -> even col 2t (uses px[t])
                ffma2(acc[2*t][0], wv0.x, px[t][c]);
                ffma2(acc[2*t][1], wv0.y, px[t][c]);
            }
            #pragma unroll
            for (int t=1;t<=RPH;t++){      // kx2 -> even col 2(t-1), kx1 -> odd col 2t-1
                ffma2(acc[2*t-2][0], wv2.x, px[t][c]);
                ffma2(acc[2*t-2][1], wv2.y, px[t][c]);
                ffma2(acc[2*t-1][0], wv1.x, px[t][c]);
                ffma2(acc[2*t-1][1], wv1.y, px[t][c]);
            }
        }
    };

    #pragma unroll 1
    for (int ci=0; ci<CI; ci+=4){
        u64 px[RPH+1][4];

        // ---- phase A: row ihyA -> even output row via ky=0 ----
        if (ihyA >= 0){
            const float* rowp = in + ((size_t)(n*Hin + ihyA)*Win)*CI;
            #pragma unroll
            for (int t=0;t<=RPH;t++){
                if (t==0 && !left){ px[0][0]=px[0][1]=px[0][2]=px[0][3]=0ull; }
                else {
                    float4 xv = *reinterpret_cast<const float4*>(rowp + (size_t)(iwb-1+t)*CI + ci);
                    px[t][0]=pack2(xv.x); px[t][1]=pack2(xv.y);
                    px[t][2]=pack2(xv.z); px[t][3]=pack2(xv.w);
                }
            }
            apply_ky(accE, 0, ci, px);
        }

        // ---- phase B: row ihyB -> even row via ky=2, odd row via ky=1 ----
        {
            const float* rowp = in + ((size_t)(n*Hin + ihyB)*Win)*CI;
            #pragma unroll
            for (int t=0;t<=RPH;t++){
                if (t==0 && !left){ px[0][0]=px[0][1]=px[0][2]=px[0][3]=0ull; }
                else {
                    float4 xv = *reinterpret_cast<const float4*>(rowp + (size_t)(iwb-1+t)*CI + ci);
                    px[t][0]=pack2(xv.x); px[t][1]=pack2(xv.y);
                    px[t][2]=pack2(xv.z); px[t][3]=pack2(xv.w);
                }
            }
            apply_ky(accE, 2, ci, px);
            apply_ky(accO, 1, ci, px);
        }
    }

    const float4 bv = *reinterpret_cast<const float4*>(bias + 4*cq);
    #pragma unroll
    for (int row=0; row<2; row++){
        const size_t ob = ((size_t)(n*Hout + h0 + row)*Wout + w0)*CO + 4*cq;
        #pragma unroll
        for (int r=0;r<RP;r++){
            u64 a0u = row ? accO[r][0] : accE[r][0];
            u64 a1u = row ? accO[r][1] : accE[r][1];
            float a0,a1,a2,a3;
            unpack2(a0,a1,a0u); unpack2(a2,a3,a1u);
            a0 += bv.x; a1 += bv.y; a2 += bv.z; a3 += bv.w;
            a0 = (a0 > 0.f) ? a0 : LRELU_ALPHA * a0;
            a1 = (a1 > 0.f) ? a1 : LRELU_ALPHA * a1;
            a2 = (a2 > 0.f) ? a2 : LRELU_ALPHA * a2;
            a3 = (a3 > 0.f) ? a3 : LRELU_ALPHA * a3;
            float4 o; o.x=a0; o.y=a1; o.z=a2; o.w=a3;
            *reinterpret_cast<float4*>(out + ob + (size_t)r*CO) = o;
        }
    }
}

// ---------------------------------------------------------------------------
// R6 row-paired deconv, RP=4, 256 threads (kept for dec1)
// ---------------------------------------------------------------------------
template<int CI, int CO>
__global__ __launch_bounds__(256) void deconv2_kernel(
    const float* __restrict__ in, const float* __restrict__ w,
    const float* __restrict__ bias, float* __restrict__ out,
    int N, int Hin, int Win, int Hout, int Wout)
{
    constexpr int RP = 4, NC = 4;
    constexpr int CQ = CO / NC;
    constexpr int G  = 256 / CQ;

    const int cq = threadIdx.x % CQ;
    const int g  = threadIdx.x / CQ;
    const int w0 = (blockIdx.x * G + g) * RP;
    const int h0 = blockIdx.y * 2;
    const int n  = blockIdx.z;
    if (w0 >= Wout) return;

    const int  iwb  = w0 >> 1;
    const bool left = (iwb >= 1);
    const int  ihyA = (h0 >> 1) - 1;
    const int  ihyB = (h0 >> 1);

    u64 acc_e[RP][2], acc_o[RP][2];
    #pragma unroll
    for (int r=0;r<RP;r++){
        acc_e[r][0]=0ull; acc_e[r][1]=0ull;
        acc_o[r][0]=0ull; acc_o[r][1]=0ull;
    }

    auto apply_ky = [&](u64 (&acc)[RP][2], const float* __restrict__ wky,
                        const u64* pm1, const u64* p0, const u64* pp1){
        #pragma unroll
        for (int c=0;c<4;c++){
            ulonglong2 wv0 = *reinterpret_cast<const ulonglong2*>(wky + (size_t)c*CO);
            ulonglong2 wv1 = *reinterpret_cast<const ulonglong2*>(wky + (size_t)(CI + c)*CO);
            ulonglong2 wv2 = *reinterpret_cast<const ulonglong2*>(wky + (size_t)(2*CI + c)*CO);
            ffma2(acc[0][0], wv0.x, pm1[c]); ffma2(acc[0][1], wv0.y, pm1[c]);
            ffma2(acc[0][0], wv2.x, p0[c]);  ffma2(acc[0][1], wv2.y, p0[c]);
            ffma2(acc[1][0], wv1.x, p0[c]);  ffma2(acc[1][1], wv1.y, p0[c]);
            ffma2(acc[2][0], wv0.x, p0[c]);  ffma2(acc[2][1], wv0.y, p0[c]);
            ffma2(acc[2][0], wv2.x, pp1[c]); ffma2(acc[2][1], wv2.y, pp1[c]);
            ffma2(acc[3][0], wv1.x, pp1[c]); ffma2(acc[3][1], wv1.y, pp1[c]);
        }
    };

    if (ihyA >= 0){
        const float* __restrict__ rowp = in + (size_t)(n*Hin + ihyA) * Win * CI;
        #pragma unroll 2
        for (int ci=0; ci<CI; ci+=4){
            u64 pm1[4], p0[4], pp1[4];
            if (left){
                float4 xm = *reinterpret_cast<const float4*>(rowp + (size_t)(iwb-1)*CI + ci);
                pm1[0]=pack2(xm.x); pm1[1]=pack2(xm.y); pm1[2]=pack2(xm.z); pm1[3]=pack2(xm.w);
            } else { pm1[0]=pm1[1]=pm1[2]=pm1[3]=0ull; }
            float4 x0 = *reinterpret_cast<const float4*>(rowp + (size_t)iwb*CI + ci);
            float4 xp = *reinterpret_cast<const float4*>(rowp + (size_t)(iwb+1)*CI + ci);
            p0[0]=pack2(x0.x); p0[1]=pack2(x0.y); p0[2]=pack2(x0.z); p0[3]=pack2(x0.w);
            pp1[0]=pack2(xp.x); pp1[1]=pack2(xp.y); pp1[2]=pack2(xp.z); pp1[3]=pack2(xp.w);
            apply_ky(acc_e, w + (size_t)(0*3*CI + ci)*CO + NC*cq, pm1, p0, pp1);
        }
    }
    {
        const float* __restrict__ rowp = in + (size_t)(n*Hin + ihyB) * Win * CI;
        #pragma unroll 2
        for (int ci=0; ci<CI; ci+=4){
            u64 pm1[4], p0[4], pp1[4];
            if (left){
                float4 xm = *reinterpret_cast<const float4*>(rowp + (size_t)(iwb-1)*CI + ci);
                pm1[0]=pack2(xm.x); pm1[1]=pack2(xm.y); pm1[2]=pack2(xm.z); pm1[3]=pack2(xm.w);
            } else { pm1[0]=pm1[1]=pm1[2]=pm1[3]=0ull; }
            float4 x0 = *reinterpret_cast<const float4*>(rowp + (size_t)iwb*CI + ci);
            float4 xp = *reinterpret_cast<const float4*>(rowp + (size_t)(iwb+1)*CI + ci);
            p0[0]=pack2(x0.x); p0[1]=pack2(x0.y); p0[2]=pack2(x0.z); p0[3]=pack2(x0.w);
            pp1[0]=pack2(xp.x); pp1[1]=pack2(xp.y); pp1[2]=pack2(xp.z); pp1[3]=pack2(xp.w);
            apply_ky(acc_e, w + (size_t)(2*3*CI + ci)*CO + NC*cq, pm1, p0, pp1);
            apply_ky(acc_o, w + (size_t)(1*3*CI + ci)*CO + NC*cq, pm1, p0, pp1);
        }
    }

    const float4 bv = *reinterpret_cast<const float4*>(bias + NC*cq);
    #pragma unroll
    for (int row=0; row<2; row++){
        u64 (&acc)[RP][2] = row ? acc_o : acc_e;
        const size_t ob = ((size_t)(n*Hout + h0 + row)*Wout + w0)*CO + NC*cq;
        #pragma unroll
        for (int r=0;r<RP;r++){
            float a0,a1,a2,a3;
            unpack2(a0,a1,acc[r][0]); unpack2(a2,a3,acc[r][1]);
            a0 += bv.x; a1 += bv.y; a2 += bv.z; a3 += bv.w;
            a0 = (a0 > 0.f) ? a0 : LRELU_ALPHA * a0;
            a1 = (a1 > 0.f) ? a1 : LRELU_ALPHA * a1;
            a2 = (a2 > 0.f) ? a2 : LRELU_ALPHA * a2;
            a3 = (a3 > 0.f) ? a3 : LRELU_ALPHA * a3;
            float4 o; o.x=a0; o.y=a1; o.z=a2; o.w=a3;
            *reinterpret_cast<float4*>(out + ob + (size_t)r*CO) = o;
        }
    }
}

// ---------------------------------------------------------------------------
// R3/R6 conv kernel (encoder): stride-2 SAME conv (pad_lo=0), 4 couts x RP cols
// ---------------------------------------------------------------------------
template<int S, int DIL, int PAD, int CI, int CO, int RP, bool RELU>
__global__ __launch_bounds__(256) void conv4_kernel(
    const float* __restrict__ in, const float* __restrict__ w,
    const float* __restrict__ bias, float* __restrict__ out,
    int N, int Hin, int Win, int Hout, int Wout)
{
    constexpr int CQ = CO / 4;
    constexpr int G  = 256 / CQ;
    static_assert(RP % 2 == 0, "RP even");

    const int cq = threadIdx.x % CQ;
    const int g  = threadIdx.x / CQ;
    const int w0 = (blockIdx.x * G + g) * RP;
    const int h  = blockIdx.y;
    const int n  = blockIdx.z;
    if (w0 >= Wout) return;

    u64 acc0[RP], acc1[RP];
    #pragma unroll
    for (int r=0;r<RP;r++){ acc0[r]=0ull; acc1[r]=0ull; }

    #pragma unroll
    for (int ky=0; ky<3; ky++){
        int ihy = h*S + ky;
        if (ihy >= Hin) continue;
        const float* __restrict__ rowp = in + (size_t)(n*Hin + ihy) * Win * CI;

        #pragma unroll
        for (int kx=0; kx<3; kx++){
            const float* __restrict__ wp = w + (size_t)((ky*3+kx)*CI) * CO + 4*cq;
            int  ofs[RP];
            bool v[RP];
            #pragma unroll
            for (int r=0;r<RP;r++){
                int iw = (w0+r)*S + kx;
                v[r]   = (iw < Win);
                ofs[r] = v[r] ? iw*CI : 0;
            }

            if constexpr (CI % 4 == 0) {
                #pragma unroll 2
                for (int ci=0; ci<CI; ci+=4){
                    ulonglong2 wv0 = *reinterpret_cast<const ulonglong2*>(wp + (size_t)(ci+0)*CO);
                    ulonglong2 wv1 = *reinterpret_cast<const ulonglong2*>(wp + (size_t)(ci+1)*CO);
                    ulonglong2 wv2 = *reinterpret_cast<const ulonglong2*>(wp + (size_t)(ci+2)*CO);
                    ulonglong2 wv3 = *reinterpret_cast<const ulonglong2*>(wp + (size_t)(ci+3)*CO);
                    #pragma unroll
                    for (int r=0;r<RP;r++){
                        if (v[r]){
                            float4 xv = *reinterpret_cast<const float4*>(rowp + ofs[r] + ci);
                            u64 p0 = pack2(xv.x), p1 = pack2(xv.y);
                            u64 p2 = pack2(xv.z), p3 = pack2(xv.w);
                            ffma2(acc0[r], wv0.x, p0); ffma2(acc1[r], wv0.y, p0);
                            ffma2(acc0[r], wv1.x, p1); ffma2(acc1[r], wv1.y, p1);
                            ffma2(acc0[r], wv2.x, p2); ffma2(acc1[r], wv2.y, p2);
                            ffma2(acc0[r], wv3.x, p3); ffma2(acc1[r], wv3.y, p3);
                        }
                    }
                }
            } else {
                #pragma unroll
                for (int ci=0; ci<CI; ci++){
                    ulonglong2 wv = *reinterpret_cast<const ulonglong2*>(wp + (size_t)ci*CO);
                    #pragma unroll
                    for (int r=0;r<RP;r++){
                        if (v[r]){
                            u64 p = pack2(rowp[ofs[r] + ci]);
                            ffma2(acc0[r], wv.x, p);
                            ffma2(acc1[r], wv.y, p);
                        }
                    }
                }
            }
        }
    }

    const float4 bv = *reinterpret_cast<const float4*>(bias + 4*cq);
    const size_t ob = ((size_t)(n*Hout + h)*Wout + w0)*CO + 4*cq;
    #pragma unroll
    for (int r=0;r<RP;r++){
        float a0,a1,a2,a3;
        unpack2(a0,a1,acc0[r]); unpack2(a2,a3,acc1[r]);
        a0 += bv.x; a1 += bv.y; a2 += bv.z; a3 += bv.w;
        if (RELU){
            a0 = (a0 > 0.f) ? a0 : LRELU_ALPHA * a0;
            a1 = (a1 > 0.f) ? a1 : LRELU_ALPHA * a1;
            a2 = (a2 > 0.f) ? a2 : LRELU_ALPHA * a2;
            a3 = (a3 > 0.f) ? a3 : LRELU_ALPHA * a3;
        }
        float4 o; o.x=a0; o.y=a1; o.z=a2; o.w=a3;
        *reinterpret_cast<float4*>(out + ob + (size_t)r*CO) = o;
    }
}

// ---------------------------------------------------------------------------
// fused enc4 (1x1 conv, 64->32) + VQ with precomputed half-norms:
// argmin_k ||z-e_k||^2 == argmin_k (0.5*||e_k||^2 - z.e_k)
// ---------------------------------------------------------------------------
__global__ __launch_bounds__(64) void enc4_vq_kernel(
    const float* __restrict__ h3, const float* __restrict__ w,
    const float* __restrict__ b, const float* __restrict__ cb,
    float* __restrict__ q, int NP)
{
    __shared__ float sw[2048];    // w  [64][32]
    __shared__ float scb[2048];   // cb [32][64]
    __shared__ float shalf[64];   // 0.5*||e_k||^2
    for (int i = threadIdx.x; i < 2048; i += 64){ sw[i] = w[i]; scb[i] = cb[i]; }
    __syncthreads();
    {
        int k = threadIdx.x;      // exactly 64 threads
        float s = 0.f;
        #pragma unroll
        for (int d=0;d<32;d++){ float e = scb[d*64 + k]; s += e*e; }
        shalf[k] = 0.5f * s;
    }
    __syncthreads();

    int p = blockIdx.x*blockDim.x + threadIdx.x;
    if (p >= NP) return;
    float z[32];
    #pragma unroll
    for (int d=0;d<32;d++) z[d] = b[d];
    const float* hp = h3 + (size_t)p*64;
    #pragma unroll
    for (int c4=0;c4<64;c4+=4){
        float4 hv = *reinterpret_cast<const float4*>(hp + c4);
        #pragma unroll
        for (int d=0;d<32;d++){
            z[d] += hv.x * sw[(c4+0)*32 + d];
            z[d] += hv.y * sw[(c4+1)*32 + d];
            z[d] += hv.z * sw[(c4+2)*32 + d];
            z[d] += hv.w * sw[(c4+3)*32 + d];
        }
    }
    float best = 3.4e38f; int bk = 0;
    for (int k=0;k<64;k++){
        float dot = 0.f;
        #pragma unroll
        for (int d=0;d<32;d++) dot += z[d] * scb[d*64 + k];
        float score = shalf[k] - dot;
        if (score < best){ best = score; bk = k; }  // strict < == first-min
    }
    float* qp = q + (size_t)p*32;
    #pragma unroll
    for (int d=0;d<32;d++) qp[d] = scb[d*64 + bk];
}

// ---------------------------------------------------------------------------
// dec4: conv_transpose stride 1 (== SAME conv pad 1), CI=32, CO=1.
// ---------------------------------------------------------------------------
__global__ __launch_bounds__(256) void dec4_kernel(
    const float* __restrict__ in, const float* __restrict__ w,
    const float* __restrict__ b, float* __restrict__ out,
    int N, int H, int W)
{
    int gw = (blockIdx.x * blockDim.x + threadIdx.x) >> 5;
    int lane = threadIdx.x & 31;
    int gpr = W >> 2;
    int total = N*H*gpr;
    if (gw >= total) return;
    int gx = gw % gpr; int t = gw / gpr;
    int h = t % H; int n = t / H;
    int w0 = gx*4;

    float wk[9];
    #pragma unroll
    for (int i=0;i<9;i++) wk[i] = w[i*32 + lane];

    float acc[4] = {0.f,0.f,0.f,0.f};
    #pragma unroll
    for (int ky=0;ky<3;ky++){
        int ih = h + ky - 1;
        if (ih < 0 || ih >= H) continue;
        const float* rowp = in + ((size_t)(n*H + ih)*W)*32 + lane;
        float v[6];
        #pragma unroll
        for (int c=0;c<6;c++){
            int iw = w0 - 1 + c;
            v[c] = (iw >= 0 && iw < W) ? rowp[(size_t)iw*32] : 0.f;
        }
        #pragma unroll
        for (int kx=0;kx<3;kx++)
            #pragma unroll
            for (int r=0;r<4;r++)
                acc[r] += v[r+kx] * wk[ky*3+kx];
    }
    float bv = b[0];
    #pragma unroll
    for (int r=0;r<4;r++){
        float a = acc[r];
        #pragma unroll
        for (int o=16;o;o>>=1) a += __shfl_xor_sync(0xffffffffu, a, o);
        if (lane == 0) out[((size_t)(n*H + h)*W) + w0 + r] = a + bv;
    }
}

extern "C" void kernel_launch(void* const* d_in, const int* in_sizes, int n_in,
                              void* d_out, int out_size)
{
    (void)in_sizes; (void)n_in; (void)out_size;
    const float* x   = (const float*)d_in[0];
    const float* e1w = (const float*)d_in[1];  const float* e1b = (const float*)d_in[2];
    const float* e2w = (const float*)d_in[3];  const float* e2b = (const float*)d_in[4];
    const float* e3w = (const float*)d_in[5];  const float* e3b = (const float*)d_in[6];
    const float* e4w = (const float*)d_in[7];  const float* e4b = (const float*)d_in[8];
    const float* cb  = (const float*)d_in[9];
    const float* d1w = (const float*)d_in[10]; const float* d1b = (const float*)d_in[11];
    const float* d2w = (const float*)d_in[12]; const float* d2b = (const float*)d_in[13];
    const float* d3w = (const float*)d_in[14]; const float* d3b = (const float*)d_in[15];
    const float* d4w = (const float*)d_in[16]; const float* d4b = (const float*)d_in[17];
    float* out = (float*)d_out;

    float *A, *B;
    cudaGetSymbolAddress((void**)&A, g_bufA);
    cudaGetSymbolAddress((void**)&B, g_bufB);

    // encoder: 256 -> 128 -> 64 -> 32   (R6 configs)
    conv4_kernel<2,1,0, 3,32,4,true ><<< dim3(1,128,32), 256 >>>(x, e1w, e1b, A, 32,256,256,128,128);
    conv4_kernel<2,1,0,32,64,4,true ><<< dim3(1, 64,32), 256 >>>(A, e2w, e2b, B, 32,128,128, 64, 64);
    conv4_kernel<2,1,0,64,64,2,true ><<< dim3(1, 32,32), 256 >>>(B, e3w, e3b, A, 32, 64, 64, 32, 32);

    // enc4 (1x1) + VQ fused
    enc4_vq_kernel<<< 512, 64 >>>(A, e4w, e4b, cb, B, 32768);

    // decoder: 32 -> 64 -> 128 -> 256
    // dec1 (small): R6 kernel, CO=64 -> CQ=16, G=16 -> 64 cols; rows 32
    deconv2_kernel<32,64><<< dim3(1, 32,32), 256 >>>(B, d1w, d1b, A, 32, 32, 32, 64, 64);
    // dec2: wide RP=8, 128 thr: CQ=16, G=8 -> 64 cols x2 blocks; rows 64
    deconvW_kernel<64,64,8><<< dim3(2, 64,32), 128 >>>(A, d2w, d2b, B, 32, 64, 64,128,128);
    // dec3: wide RP=8, 128 thr: CQ=8, G=16 -> 128 cols x2 blocks; rows 128
    deconvW_kernel<64,32,8><<< dim3(2,128,32), 128 >>>(B, d3w, d3b, A, 32,128,128,256,256);

    // dec4: stride-1 deconv == SAME conv, CO=1
    dec4_kernel<<< 65536, 256 >>>(A, d4w, d4b, out, 32, 256, 256);
}

// round 9
// speedup vs baseline: 1.4318x; 1.0580x over previous
#include <cuda_runtime.h>
#include <cstdint>

#define LRELU_ALPHA 0.2f

typedef unsigned long long u64;

// packed f32x2 helpers (sm_103a FFMA2 is PTX-only)
__device__ __forceinline__ void ffma2(u64 &d, u64 a, u64 b){
    asm("fma.rn.f32x2 %0, %1, %2, %0;" : "+l"(d) : "l"(a), "l"(b));
}
__device__ __forceinline__ u64 pack2(float s){
    u64 d; asm("mov.b64 %0, {%1, %1};" : "=l"(d) : "f"(s)); return d;
}
__device__ __forceinline__ void unpack2(float &lo, float &hi, u64 v){
    asm("mov.b64 {%0,%1}, %2;" : "=f"(lo), "=f"(hi) : "l"(v));
}

// ping-pong activation buffers (allocation-free scratch)
__device__ __align__(16) float g_bufA[67108864];   // h1, h3, d1, d3
__device__ __align__(16) float g_bufB[33554432];   // h2, q,  d2

// ---------------------------------------------------------------------------
// Wide row-paired stride-2 transposed conv (lhs_dilation=2, pad=(2,1)), NHWC,
// w HWIO [9][CI][CO], weights from GLOBAL (L1-broadcast across the warp).
// Thread = 4 couts x RP output cols x 2 output rows (h0 even, h0+1 odd).
// x columns iwb-1 .. iwb+RP/2-1 packed ONCE per ci-chunk per input row and
// reused by both ky-applications of that row.
// ---------------------------------------------------------------------------
template<int CI, int CO, int RP>
__global__ __launch_bounds__(128,3) void deconvW_kernel(
    const float* __restrict__ in, const float* __restrict__ w,
    const float* __restrict__ bias, float* __restrict__ out,
    int N, int Hin, int Win, int Hout, int Wout)
{
    constexpr int NC  = 4;
    constexpr int CQ  = CO / NC;
    constexpr int G   = 128 / CQ;
    constexpr int RPH = RP / 2;

    const int cq = threadIdx.x % CQ;
    const int g  = threadIdx.x / CQ;
    const int w0 = (blockIdx.x * G + g) * RP;
    const int h0 = blockIdx.y * 2;
    const int n  = blockIdx.z;

    const int  iwb  = w0 >> 1;
    const bool left = (iwb >= 1);
    const int  ihyA = (h0 >> 1) - 1;
    const int  ihyB = (h0 >> 1);

    u64 accE[RP][2], accO[RP][2];
    #pragma unroll
    for (int r=0;r<RP;r++){
        accE[r][0]=0ull; accE[r][1]=0ull;
        accO[r][0]=0ull; accO[r][1]=0ull;
    }

    const float* __restrict__ wp = w + 4*cq;

    auto apply_ky = [&](u64 (&acc)[RP][2], int ky, int ci, const u64 (*px)[4]){
        #pragma unroll
        for (int c=0;c<4;c++){
            ulonglong2 wv0 = *reinterpret_cast<const ulonglong2*>(wp + (size_t)((ky*3+0)*CI + ci + c)*CO);
            ulonglong2 wv1 = *reinterpret_cast<const ulonglong2*>(wp + (size_t)((ky*3+1)*CI + ci + c)*CO);
            ulonglong2 wv2 = *reinterpret_cast<const ulonglong2*>(wp + (size_t)((ky*3+2)*CI + ci + c)*CO);
            #pragma unroll
            for (int t=0;t<RPH;t++){
                ffma2(acc[2*t][0], wv0.x, px[t][c]);
                ffma2(acc[2*t][1], wv0.y, px[t][c]);
            }
            #pragma unroll
            for (int t=1;t<=RPH;t++){
                ffma2(acc[2*t-2][0], wv2.x, px[t][c]);
                ffma2(acc[2*t-2][1], wv2.y, px[t][c]);
                ffma2(acc[2*t-1][0], wv1.x, px[t][c]);
                ffma2(acc[2*t-1][1], wv1.y, px[t][c]);
            }
        }
    };

    #pragma unroll 1
    for (int ci=0; ci<CI; ci+=4){
        u64 px[RPH+1][4];

        if (ihyA >= 0){
            const float* rowp = in + ((size_t)(n*Hin + ihyA)*Win)*CI;
            #pragma unroll
            for (int t=0;t<=RPH;t++){
                if (t==0 && !left){ px[0][0]=px[0][1]=px[0][2]=px[0][3]=0ull; }
                else {
                    float4 xv = *reinterpret_cast<const float4*>(rowp + (size_t)(iwb-1+t)*CI + ci);
                    px[t][0]=pack2(xv.x); px[t][1]=pack2(xv.y);
                    px[t][2]=pack2(xv.z); px[t][3]=pack2(xv.w);
                }
            }
            apply_ky(accE, 0, ci, px);
        }
        {
            const float* rowp = in + ((size_t)(n*Hin + ihyB)*Win)*CI;
            #pragma unroll
            for (int t=0;t<=RPH;t++){
                if (t==0 && !left){ px[0][0]=px[0][1]=px[0][2]=px[0][3]=0ull; }
                else {
                    float4 xv = *reinterpret_cast<const float4*>(rowp + (size_t)(iwb-1+t)*CI + ci);
                    px[t][0]=pack2(xv.x); px[t][1]=pack2(xv.y);
                    px[t][2]=pack2(xv.z); px[t][3]=pack2(xv.w);
                }
            }
            apply_ky(accE, 2, ci, px);
            apply_ky(accO, 1, ci, px);
        }
    }

    const float4 bv = *reinterpret_cast<const float4*>(bias + 4*cq);
    #pragma unroll
    for (int row=0; row<2; row++){
        const size_t ob = ((size_t)(n*Hout + h0 + row)*Wout + w0)*CO + 4*cq;
        #pragma unroll
        for (int r=0;r<RP;r++){
            u64 a0u = row ? accO[r][0] : accE[r][0];
            u64 a1u = row ? accO[r][1] : accE[r][1];
            float a0,a1,a2,a3;
            unpack2(a0,a1,a0u); unpack2(a2,a3,a1u);
            a0 += bv.x; a1 += bv.y; a2 += bv.z; a3 += bv.w;
            a0 = (a0 > 0.f) ? a0 : LRELU_ALPHA * a0;
            a1 = (a1 > 0.f) ? a1 : LRELU_ALPHA * a1;
            a2 = (a2 > 0.f) ? a2 : LRELU_ALPHA * a2;
            a3 = (a3 > 0.f) ? a3 : LRELU_ALPHA * a3;
            float4 o; o.x=a0; o.y=a1; o.z=a2; o.w=a3;
            *reinterpret_cast<float4*>(out + ob + (size_t)r*CO) = o;
        }
    }
}

// ---------------------------------------------------------------------------
// Encoder conv: stride-2 SAME conv (pad_lo=0), thread = 4 couts x RP cols.
// NT = block size (128 -> 3 CTAs/SM latency-hiding config; 256 for enc1).
// ---------------------------------------------------------------------------
template<int CI, int CO, int RP, int NT>
__global__ __launch_bounds__(NT, NT==128 ? 3 : 1) void convE_kernel(
    const float* __restrict__ in, const float* __restrict__ w,
    const float* __restrict__ bias, float* __restrict__ out,
    int N, int Hin, int Win, int Hout, int Wout)
{
    constexpr int CQ = CO / 4;
    constexpr int G  = NT / CQ;
    static_assert(RP % 2 == 0, "RP even");

    const int cq = threadIdx.x % CQ;
    const int g  = threadIdx.x / CQ;
    const int w0 = (blockIdx.x * G + g) * RP;
    const int h  = blockIdx.y;
    const int n  = blockIdx.z;
    if (w0 >= Wout) return;

    u64 acc0[RP], acc1[RP];
    #pragma unroll
    for (int r=0;r<RP;r++){ acc0[r]=0ull; acc1[r]=0ull; }

    #pragma unroll
    for (int ky=0; ky<3; ky++){
        int ihy = h*2 + ky;
        if (ihy >= Hin) continue;
        const float* __restrict__ rowp = in + (size_t)(n*Hin + ihy) * Win * CI;

        #pragma unroll
        for (int kx=0; kx<3; kx++){
            const float* __restrict__ wp = w + (size_t)((ky*3+kx)*CI) * CO + 4*cq;
            int  ofs[RP];
            bool v[RP];
            #pragma unroll
            for (int r=0;r<RP;r++){
                int iw = (w0+r)*2 + kx;
                v[r]   = (iw < Win);
                ofs[r] = v[r] ? iw*CI : 0;
            }

            if constexpr (CI % 4 == 0) {
                #pragma unroll 2
                for (int ci=0; ci<CI; ci+=4){
                    ulonglong2 wv0 = *reinterpret_cast<const ulonglong2*>(wp + (size_t)(ci+0)*CO);
                    ulonglong2 wv1 = *reinterpret_cast<const ulonglong2*>(wp + (size_t)(ci+1)*CO);
                    ulonglong2 wv2 = *reinterpret_cast<const ulonglong2*>(wp + (size_t)(ci+2)*CO);
                    ulonglong2 wv3 = *reinterpret_cast<const ulonglong2*>(wp + (size_t)(ci+3)*CO);
                    #pragma unroll
                    for (int r=0;r<RP;r++){
                        if (v[r]){
                            float4 xv = *reinterpret_cast<const float4*>(rowp + ofs[r] + ci);
                            u64 p0 = pack2(xv.x), p1 = pack2(xv.y);
                            u64 p2 = pack2(xv.z), p3 = pack2(xv.w);
                            ffma2(acc0[r], wv0.x, p0); ffma2(acc1[r], wv0.y, p0);
                            ffma2(acc0[r], wv1.x, p1); ffma2(acc1[r], wv1.y, p1);
                            ffma2(acc0[r], wv2.x, p2); ffma2(acc1[r], wv2.y, p2);
                            ffma2(acc0[r], wv3.x, p3); ffma2(acc1[r], wv3.y, p3);
                        }
                    }
                }
            } else {
                #pragma unroll
                for (int ci=0; ci<CI; ci++){
                    ulonglong2 wv = *reinterpret_cast<const ulonglong2*>(wp + (size_t)ci*CO);
                    #pragma unroll
                    for (int r=0;r<RP;r++){
                        if (v[r]){
                            u64 p = pack2(rowp[ofs[r] + ci]);
                            ffma2(acc0[r], wv.x, p);
                            ffma2(acc1[r], wv.y, p);
                        }
                    }
                }
            }
        }
    }

    const float4 bv = *reinterpret_cast<const float4*>(bias + 4*cq);
    const size_t ob = ((size_t)(n*Hout + h)*Wout + w0)*CO + 4*cq;
    #pragma unroll
    for (int r=0;r<RP;r++){
        float a0,a1,a2,a3;
        unpack2(a0,a1,acc0[r]); unpack2(a2,a3,acc1[r]);
        a0 += bv.x; a1 += bv.y; a2 += bv.z; a3 += bv.w;
        a0 = (a0 > 0.f) ? a0 : LRELU_ALPHA * a0;
        a1 = (a1 > 0.f) ? a1 : LRELU_ALPHA * a1;
        a2 = (a2 > 0.f) ? a2 : LRELU_ALPHA * a2;
        a3 = (a3 > 0.f) ? a3 : LRELU_ALPHA * a3;
        float4 o; o.x=a0; o.y=a1; o.z=a2; o.w=a3;
        *reinterpret_cast<float4*>(out + ob + (size_t)r*CO) = o;
    }
}

// ---------------------------------------------------------------------------
// fused enc4 (1x1 conv, 64->32) + VQ with precomputed half-norms
// ---------------------------------------------------------------------------
__global__ __launch_bounds__(64) void enc4_vq_kernel(
    const float* __restrict__ h3, const float* __restrict__ w,
    const float* __restrict__ b, const float* __restrict__ cb,
    float* __restrict__ q, int NP)
{
    __shared__ float sw[2048];    // w  [64][32]
    __shared__ float scb[2048];   // cb [32][64]
    __shared__ float shalf[64];   // 0.5*||e_k||^2
    for (int i = threadIdx.x; i < 2048; i += 64){ sw[i] = w[i]; scb[i] = cb[i]; }
    __syncthreads();
    {
        int k = threadIdx.x;
        float s = 0.f;
        #pragma unroll
        for (int d=0;d<32;d++){ float e = scb[d*64 + k]; s += e*e; }
        shalf[k] = 0.5f * s;
    }
    __syncthreads();

    int p = blockIdx.x*blockDim.x + threadIdx.x;
    if (p >= NP) return;
    float z[32];
    #pragma unroll
    for (int d=0;d<32;d++) z[d] = b[d];
    const float* hp = h3 + (size_t)p*64;
    #pragma unroll
    for (int c4=0;c4<64;c4+=4){
        float4 hv = *reinterpret_cast<const float4*>(hp + c4);
        #pragma unroll
        for (int d=0;d<32;d++){
            z[d] += hv.x * sw[(c4+0)*32 + d];
            z[d] += hv.y * sw[(c4+1)*32 + d];
            z[d] += hv.z * sw[(c4+2)*32 + d];
            z[d] += hv.w * sw[(c4+3)*32 + d];
        }
    }
    float best = 3.4e38f; int bk = 0;
    for (int k=0;k<64;k++){
        float dot = 0.f;
        #pragma unroll
        for (int d=0;d<32;d++) dot += z[d] * scb[d*64 + k];
        float score = shalf[k] - dot;
        if (score < best){ best = score; bk = k; }  // strict < == first-min
    }
    float* qp = q + (size_t)p*32;
    #pragma unroll
    for (int d=0;d<32;d++) qp[d] = scb[d*64 + bk];
}

// ---------------------------------------------------------------------------
// dec4: conv_transpose stride 1 (== SAME conv pad 1), CI=32, CO=1.
// ---------------------------------------------------------------------------
__global__ __launch_bounds__(256) void dec4_kernel(
    const float* __restrict__ in, const float* __restrict__ w,
    const float* __restrict__ b, float* __restrict__ out,
    int N, int H, int W)
{
    int gw = (blockIdx.x * blockDim.x + threadIdx.x) >> 5;
    int lane = threadIdx.x & 31;
    int gpr = W >> 2;
    int total = N*H*gpr;
    if (gw >= total) return;
    int gx = gw % gpr; int t = gw / gpr;
    int h = t % H; int n = t / H;
    int w0 = gx*4;

    float wk[9];
    #pragma unroll
    for (int i=0;i<9;i++) wk[i] = w[i*32 + lane];

    float acc[4] = {0.f,0.f,0.f,0.f};
    #pragma unroll
    for (int ky=0;ky<3;ky++){
        int ih = h + ky - 1;
        if (ih < 0 || ih >= H) continue;
        const float* rowp = in + ((size_t)(n*H + ih)*W)*32 + lane;
        float v[6];
        #pragma unroll
        for (int c=0;c<6;c++){
            int iw = w0 - 1 + c;
            v[c] = (iw >= 0 && iw < W) ? rowp[(size_t)iw*32] : 0.f;
        }
        #pragma unroll
        for (int kx=0;kx<3;kx++)
            #pragma unroll
            for (int r=0;r<4;r++)
                acc[r] += v[r+kx] * wk[ky*3+kx];
    }
    float bv = b[0];
    #pragma unroll
    for (int r=0;r<4;r++){
        float a = acc[r];
        #pragma unroll
        for (int o=16;o;o>>=1) a += __shfl_xor_sync(0xffffffffu, a, o);
        if (lane == 0) out[((size_t)(n*H + h)*W) + w0 + r] = a + bv;
    }
}

extern "C" void kernel_launch(void* const* d_in, const int* in_sizes, int n_in,
                              void* d_out, int out_size)
{
    (void)in_sizes; (void)n_in; (void)out_size;
    const float* x   = (const float*)d_in[0];
    const float* e1w = (const float*)d_in[1];  const float* e1b = (const float*)d_in[2];
    const float* e2w = (const float*)d_in[3];  const float* e2b = (const float*)d_in[4];
    const float* e3w = (const float*)d_in[5];  const float* e3b = (const float*)d_in[6];
    const float* e4w = (const float*)d_in[7];  const float* e4b = (const float*)d_in[8];
    const float* cb  = (const float*)d_in[9];
    const float* d1w = (const float*)d_in[10]; const float* d1b = (const float*)d_in[11];
    const float* d2w = (const float*)d_in[12]; const float* d2b = (const float*)d_in[13];
    const float* d3w = (const float*)d_in[14]; const float* d3b = (const float*)d_in[15];
    const float* d4w = (const float*)d_in[16]; const float* d4b = (const float*)d_in[17];
    float* out = (float*)d_out;

    float *A, *B;
    cudaGetSymbolAddress((void**)&A, g_bufA);
    cudaGetSymbolAddress((void**)&B, g_bufB);

    // encoder: 256 -> 128 -> 64 -> 32
    // enc1: CI=3 scalar path, 256 thr (CQ=8, G=32 -> 128 cols @ RP=4)
    convE_kernel<3,32,4,256><<< dim3(1,128,32), 256 >>>(x, e1w, e1b, A, 32,256,256,128,128);
    // enc2: 128 thr, RP=8: CQ=16, G=8 -> 64 cols
    convE_kernel<32,64,8,128><<< dim3(1,64,32), 128 >>>(A, e2w, e2b, B, 32,128,128, 64, 64);
    // enc3: 128 thr, RP=4: CQ=16, G=8 -> 32 cols
    convE_kernel<64,64,4,128><<< dim3(1,32,32), 128 >>>(B, e3w, e3b, A, 32, 64, 64, 32, 32);

    // enc4 (1x1) + VQ fused
    enc4_vq_kernel<<< 512, 64 >>>(A, e4w, e4b, cb, B, 32768);

    // decoder: 32 -> 64 -> 128 -> 256 (all deconvW, the R8 winner recipe)
    // dec1: CQ=16, G=8 -> 64 cols @ RP=8; rows 32
    deconvW_kernel<32,64,8><<< dim3(1, 32,32), 128 >>>(B, d1w, d1b, A, 32, 32, 32, 64, 64);
    // dec2: CQ=16, G=8 -> 64 cols x2 blocks; rows 64
    deconvW_kernel<64,64,8><<< dim3(2, 64,32), 128 >>>(A, d2w, d2b, B, 32, 64, 64,128,128);
    // dec3: CQ=8, G=16 -> 128 cols x2 blocks; rows 128
    deconvW_kernel<64,32,8><<< dim3(2,128,32), 128 >>>(B, d3w, d3b, A, 32,128,128,256,256);

    // dec4: stride-1 deconv == SAME conv, CO=1
    dec4_kernel<<< 65536, 256 >>>(A, d4w, d4b, out, 32, 256, 256);
}